// round 2
// baseline (speedup 1.0000x reference)
#include <cuda_runtime.h>

#define N_NODES 50000
#define D_IN    256
#define D_OUT   128
#define N_POS   1600000
#define N_PRED  500000

// Scratch (allocation-free rule: device globals)
__device__ float g_W2[D_IN * D_OUT];           // fused weight W1@Wc
__device__ float g_c2[D_OUT];                  // fused bias b1@Wc
__device__ float g_h[(size_t)N_NODES * D_OUT]; // x@W2 + c2
__device__ float g_outf[(size_t)N_NODES * D_OUT]; // aggregated node embeddings
__device__ float g_deg[N_NODES];
__device__ float g_dinv[N_NODES];

// ---------------------------------------------------------------- weight fuse
__global__ void k_fuse(const float* __restrict__ W1, const float* __restrict__ Wc,
                       const float* __restrict__ b1) {
    int idx = blockIdx.x * blockDim.x + threadIdx.x;
    if (idx >= D_IN * D_OUT) return;
    int k = idx >> 7, j = idx & 127;
    float acc = 0.f;
    #pragma unroll 8
    for (int m = 0; m < D_IN; ++m)
        acc = fmaf(W1[k * D_IN + m], Wc[m * D_OUT + j], acc);
    g_W2[idx] = acc;
    if (idx < D_OUT) {
        float c = 0.f;
        for (int m = 0; m < D_IN; ++m)
            c = fmaf(b1[m], Wc[m * D_OUT + idx], c);
        g_c2[idx] = c;
    }
}

// ---------------------------------------------------------------- degree/norm
__global__ void k_deg_init() {
    int i = blockIdx.x * blockDim.x + threadIdx.x;
    if (i < N_NODES) g_deg[i] = 1.0f;  // self loop
}

__global__ void k_deg_acc(const int* __restrict__ pos) {
    int e = blockIdx.x * blockDim.x + threadIdx.x;
    if (e < N_POS) atomicAdd(&g_deg[pos[N_POS + e]], 1.0f);
}

__global__ void k_dinv() {
    int i = blockIdx.x * blockDim.x + threadIdx.x;
    if (i < N_NODES) g_dinv[i] = rsqrtf(g_deg[i]);  // deg >= 1 always
}

// ---------------------------------------------------------------- GEMM h = x @ W2 + c2
// Tile: BM=64 rows, full N=128, BK=16. 256 threads, each computes 4x8 outputs.
#define BM 64
#define BK 16
__global__ __launch_bounds__(256) void k_gemm(const float* __restrict__ x) {
    __shared__ float sx[BK][BM + 1];   // x tile, transposed (k-major)
    __shared__ float sw[BK][D_OUT];    // W2 tile

    int tid = threadIdx.x;
    int tx = tid & 15;   // col group (0..15) -> 8 cols each
    int ty = tid >> 4;   // row group (0..15) -> 4 rows each
    int row0 = blockIdx.x * BM;

    float acc[4][8];
    #pragma unroll
    for (int i = 0; i < 4; ++i)
        #pragma unroll
        for (int j = 0; j < 8; ++j) acc[i][j] = 0.f;

    int lm = tid >> 2;         // x-load: row within tile (0..63)
    int lk = (tid & 3) * 4;    // x-load: k offset (0,4,8,12)
    int wk = tid >> 5;         // w-load: k row (0..7)
    int wj = (tid & 31) * 4;   // w-load: col offset

    for (int k0 = 0; k0 < D_IN; k0 += BK) {
        int grow = row0 + lm;
        float4 xv = make_float4(0.f, 0.f, 0.f, 0.f);
        if (grow < N_NODES)
            xv = *(const float4*)(x + (size_t)grow * D_IN + k0 + lk);
        sx[lk + 0][lm] = xv.x; sx[lk + 1][lm] = xv.y;
        sx[lk + 2][lm] = xv.z; sx[lk + 3][lm] = xv.w;

        *(float4*)&sw[wk][wj]     = *(const float4*)&g_W2[(k0 + wk) * D_OUT + wj];
        *(float4*)&sw[wk + 8][wj] = *(const float4*)&g_W2[(k0 + wk + 8) * D_OUT + wj];
        __syncthreads();

        #pragma unroll
        for (int kk = 0; kk < BK; ++kk) {
            float aa[4];
            #pragma unroll
            for (int i = 0; i < 4; ++i) aa[i] = sx[kk][ty * 4 + i];
            const float4* swr = (const float4*)&sw[kk][0];
            float4 b0 = swr[tx * 2], b1v = swr[tx * 2 + 1];
            float bb[8] = {b0.x, b0.y, b0.z, b0.w, b1v.x, b1v.y, b1v.z, b1v.w};
            #pragma unroll
            for (int i = 0; i < 4; ++i)
                #pragma unroll
                for (int j = 0; j < 8; ++j)
                    acc[i][j] = fmaf(aa[i], bb[j], acc[i][j]);
        }
        __syncthreads();
    }

    float4 c2a = *(const float4*)&g_c2[tx * 8];
    float4 c2b = *(const float4*)&g_c2[tx * 8 + 4];
    #pragma unroll
    for (int i = 0; i < 4; ++i) {
        int row = row0 + ty * 4 + i;
        if (row >= N_NODES) continue;
        float4 o0 = make_float4(acc[i][0] + c2a.x, acc[i][1] + c2a.y,
                                acc[i][2] + c2a.z, acc[i][3] + c2a.w);
        float4 o1 = make_float4(acc[i][4] + c2b.x, acc[i][5] + c2b.y,
                                acc[i][6] + c2b.z, acc[i][7] + c2b.w);
        *(float4*)&g_h[(size_t)row * D_OUT + tx * 8]     = o0;
        *(float4*)&g_h[(size_t)row * D_OUT + tx * 8 + 4] = o1;
    }
}

// ---------------------------------------------------------------- out init: bc + dinv^2 * h (self loop)
__global__ void k_init_out(const float* __restrict__ bc) {
    int idx = blockIdx.x * blockDim.x + threadIdx.x;   // over N_NODES*32 float4s
    if (idx >= N_NODES * 32) return;
    int node = idx >> 5, c = idx & 31;
    float d = g_dinv[node];
    float w = d * d;
    float4 hv = ((const float4*)g_h)[idx];
    float4 bv = ((const float4*)bc)[c];
    float4 o = make_float4(bv.x + w * hv.x, bv.y + w * hv.y,
                           bv.z + w * hv.z, bv.w + w * hv.w);
    ((float4*)g_outf)[idx] = o;
}

// ---------------------------------------------------------------- edge scatter: one warp per edge
__global__ __launch_bounds__(256) void k_scatter(const int* __restrict__ pos) {
    int gw = (blockIdx.x * blockDim.x + threadIdx.x) >> 5;
    int lane = threadIdx.x & 31;
    if (gw >= N_POS) return;
    int r = pos[gw];            // source (broadcast load)
    int c = pos[N_POS + gw];    // target
    float w = g_dinv[r] * g_dinv[c];
    float4 hv = ((const float4*)g_h)[(size_t)r * 32 + lane];
    float4* dst = (float4*)(g_outf + (size_t)c * D_OUT + lane * 4);
    atomicAdd(dst, make_float4(w * hv.x, w * hv.y, w * hv.z, w * hv.w));
}

// ---------------------------------------------------------------- edge scoring: one warp per edge
__global__ __launch_bounds__(256) void k_score(const int* __restrict__ ei,
                                               float* __restrict__ logits) {
    int gw = (blockIdx.x * blockDim.x + threadIdx.x) >> 5;
    int lane = threadIdx.x & 31;
    if (gw >= N_PRED) return;
    int a = ei[gw];
    int b = ei[N_PRED + gw];
    float4 va = ((const float4*)g_outf)[(size_t)a * 32 + lane];
    float4 vb = ((const float4*)g_outf)[(size_t)b * 32 + lane];
    float p = va.x * vb.x + va.y * vb.y + va.z * vb.z + va.w * vb.w;
    #pragma unroll
    for (int o = 16; o; o >>= 1) p += __shfl_xor_sync(0xFFFFFFFFu, p, o);
    if (lane == 0) logits[gw] = p;
}

// ----------------------------------------------------------------
extern "C" void kernel_launch(void* const* d_in, const int* in_sizes, int n_in,
                              void* d_out, int out_size) {
    const float* x   = (const float*)d_in[0];
    const int*   ei  = (const int*)d_in[1];   // edge_index [2, N_PRED]
    const int*   pos = (const int*)d_in[2];   // pos_edge_index [2, N_POS]
    const float* W1  = (const float*)d_in[3];
    const float* b1  = (const float*)d_in[4];
    const float* Wc  = (const float*)d_in[5];
    const float* bc  = (const float*)d_in[6];
    float* logits = (float*)d_out;

    k_fuse<<<(D_IN * D_OUT + 255) / 256, 256>>>(W1, Wc, b1);
    k_deg_init<<<(N_NODES + 255) / 256, 256>>>();
    k_deg_acc<<<(N_POS + 255) / 256, 256>>>(pos);
    k_dinv<<<(N_NODES + 255) / 256, 256>>>();
    k_gemm<<<(N_NODES + BM - 1) / BM, 256>>>(x);
    k_init_out<<<(N_NODES * 32 + 255) / 256, 256>>>(bc);
    k_scatter<<<(N_POS * 32 + 255) / 256, 256>>>(pos);
    k_score<<<(N_PRED * 32 + 255) / 256, 256>>>(ei, logits);
}

// round 3
// speedup vs baseline: 1.0950x; 1.0950x over previous
#include <cuda_runtime.h>

#define N_NODES 50000
#define D_IN    256
#define D_OUT   128
#define N_POS   1600000
#define N_PRED  500000

// Scratch (allocation-free rule: device globals)
__device__ float g_W2[D_IN * D_OUT];              // fused weight W1@Wc
__device__ float g_c2[D_OUT];                     // fused bias b1@Wc
__device__ float g_h[(size_t)N_NODES * D_OUT];    // x@W2 + c2
__device__ float g_outf[(size_t)N_NODES * D_OUT]; // aggregated node embeddings
__device__ float g_dinv[N_NODES];
__device__ int   g_cnt[N_NODES];                  // in-degree (excl self loop)
__device__ int   g_off[N_NODES];                  // CSR offsets
__device__ int   g_cursor[N_NODES];               // fill cursors
__device__ int   g_srcs[N_POS];                   // CSR source list

// ---------------------------------------------------------------- weight fuse
__global__ void k_fuse(const float* __restrict__ W1, const float* __restrict__ Wc,
                       const float* __restrict__ b1) {
    int idx = blockIdx.x * blockDim.x + threadIdx.x;
    if (idx >= D_IN * D_OUT) return;
    int k = idx >> 7, j = idx & 127;
    float acc = 0.f;
    #pragma unroll 8
    for (int m = 0; m < D_IN; ++m)
        acc = fmaf(W1[k * D_IN + m], Wc[m * D_OUT + j], acc);
    g_W2[idx] = acc;
    if (idx < D_OUT) {
        float c = 0.f;
        for (int m = 0; m < D_IN; ++m)
            c = fmaf(b1[m], Wc[m * D_OUT + idx], c);
        g_c2[idx] = c;
    }
}

// ---------------------------------------------------------------- degree count
__global__ void k_zero_cnt() {
    int i = blockIdx.x * blockDim.x + threadIdx.x;
    if (i < N_NODES) g_cnt[i] = 0;
}

__global__ void k_count(const int* __restrict__ pos) {
    int e = blockIdx.x * blockDim.x + threadIdx.x;
    if (e < N_POS) atomicAdd(&g_cnt[pos[N_POS + e]], 1);
}

// ---------------------------------------------------------------- scan (+dinv)
// Single block, 1024 threads: exclusive prefix sum over g_cnt -> g_off/g_cursor,
// and dinv = rsqrt(cnt + 1) on the way.
__global__ __launch_bounds__(1024) void k_scan() {
    __shared__ int s[1024];
    int tid = threadIdx.x;
    int running = 0;
    for (int base = 0; base < N_NODES; base += 1024) {
        int i = base + tid;
        int v = (i < N_NODES) ? g_cnt[i] : 0;
        s[tid] = v;
        __syncthreads();
        #pragma unroll
        for (int off = 1; off < 1024; off <<= 1) {
            int t = (tid >= off) ? s[tid - off] : 0;
            __syncthreads();
            s[tid] += t;
            __syncthreads();
        }
        int excl = s[tid] - v;
        if (i < N_NODES) {
            int o = running + excl;
            g_off[i] = o;
            g_cursor[i] = o;
            g_dinv[i] = rsqrtf((float)v + 1.0f);
        }
        running += s[1023];
        __syncthreads();
    }
}

// ---------------------------------------------------------------- CSR fill
__global__ void k_fill(const int* __restrict__ pos) {
    int e = blockIdx.x * blockDim.x + threadIdx.x;
    if (e >= N_POS) return;
    int r = pos[e];
    int c = pos[N_POS + e];
    int p = atomicAdd(&g_cursor[c], 1);
    g_srcs[p] = r;
}

// ---------------------------------------------------------------- GEMM h = x @ W2 + c2
// Tile: BM=64 rows, full N=128, BK=16. 256 threads, each computes 4x8 outputs.
#define BM 64
#define BK 16
__global__ __launch_bounds__(256) void k_gemm(const float* __restrict__ x) {
    __shared__ float sx[BK][BM + 1];   // x tile, transposed (k-major)
    __shared__ float sw[BK][D_OUT];    // W2 tile

    int tid = threadIdx.x;
    int tx = tid & 15;   // col group (0..15) -> 8 cols each
    int ty = tid >> 4;   // row group (0..15) -> 4 rows each
    int row0 = blockIdx.x * BM;

    float acc[4][8];
    #pragma unroll
    for (int i = 0; i < 4; ++i)
        #pragma unroll
        for (int j = 0; j < 8; ++j) acc[i][j] = 0.f;

    int lm = tid >> 2;         // x-load: row within tile (0..63)
    int lk = (tid & 3) * 4;    // x-load: k offset (0,4,8,12)
    int wk = tid >> 5;         // w-load: k row (0..7)
    int wj = (tid & 31) * 4;   // w-load: col offset

    for (int k0 = 0; k0 < D_IN; k0 += BK) {
        int grow = row0 + lm;
        float4 xv = make_float4(0.f, 0.f, 0.f, 0.f);
        if (grow < N_NODES)
            xv = *(const float4*)(x + (size_t)grow * D_IN + k0 + lk);
        sx[lk + 0][lm] = xv.x; sx[lk + 1][lm] = xv.y;
        sx[lk + 2][lm] = xv.z; sx[lk + 3][lm] = xv.w;

        *(float4*)&sw[wk][wj]     = *(const float4*)&g_W2[(k0 + wk) * D_OUT + wj];
        *(float4*)&sw[wk + 8][wj] = *(const float4*)&g_W2[(k0 + wk + 8) * D_OUT + wj];
        __syncthreads();

        #pragma unroll
        for (int kk = 0; kk < BK; ++kk) {
            float aa[4];
            #pragma unroll
            for (int i = 0; i < 4; ++i) aa[i] = sx[kk][ty * 4 + i];
            const float4* swr = (const float4*)&sw[kk][0];
            float4 b0 = swr[tx * 2], b1v = swr[tx * 2 + 1];
            float bb[8] = {b0.x, b0.y, b0.z, b0.w, b1v.x, b1v.y, b1v.z, b1v.w};
            #pragma unroll
            for (int i = 0; i < 4; ++i)
                #pragma unroll
                for (int j = 0; j < 8; ++j)
                    acc[i][j] = fmaf(aa[i], bb[j], acc[i][j]);
        }
        __syncthreads();
    }

    float4 c2a = *(const float4*)&g_c2[tx * 8];
    float4 c2b = *(const float4*)&g_c2[tx * 8 + 4];
    #pragma unroll
    for (int i = 0; i < 4; ++i) {
        int row = row0 + ty * 4 + i;
        if (row >= N_NODES) continue;
        float4 o0 = make_float4(acc[i][0] + c2a.x, acc[i][1] + c2a.y,
                                acc[i][2] + c2a.z, acc[i][3] + c2a.w);
        float4 o1 = make_float4(acc[i][4] + c2b.x, acc[i][5] + c2b.y,
                                acc[i][6] + c2b.z, acc[i][7] + c2b.w);
        *(float4*)&g_h[(size_t)row * D_OUT + tx * 8]     = o0;
        *(float4*)&g_h[(size_t)row * D_OUT + tx * 8 + 4] = o1;
    }
}

// ---------------------------------------------------------------- aggregate: one warp per node (gather)
// out[c] = bc + dinv[c] * ( dinv[c]*h[c] + sum_r dinv[r]*h[r] )
__global__ __launch_bounds__(256) void k_aggregate(const float* __restrict__ bc) {
    int node = (blockIdx.x * blockDim.x + threadIdx.x) >> 5;
    int lane = threadIdx.x & 31;
    if (node >= N_NODES) return;

    float dc = g_dinv[node];
    float4 hv = ((const float4*)g_h)[(size_t)node * 32 + lane];
    float4 acc = make_float4(dc * hv.x, dc * hv.y, dc * hv.z, dc * hv.w);

    int s0 = g_off[node];
    int cnt = g_cnt[node];
    #pragma unroll 2
    for (int j = 0; j < cnt; ++j) {
        int r = g_srcs[s0 + j];            // broadcast load
        float w = g_dinv[r];               // broadcast load
        float4 v = ((const float4*)g_h)[(size_t)r * 32 + lane];
        acc.x = fmaf(w, v.x, acc.x);
        acc.y = fmaf(w, v.y, acc.y);
        acc.z = fmaf(w, v.z, acc.z);
        acc.w = fmaf(w, v.w, acc.w);
    }

    float4 bv = ((const float4*)bc)[lane];
    float4 o = make_float4(fmaf(dc, acc.x, bv.x), fmaf(dc, acc.y, bv.y),
                           fmaf(dc, acc.z, bv.z), fmaf(dc, acc.w, bv.w));
    ((float4*)g_outf)[(size_t)node * 32 + lane] = o;
}

// ---------------------------------------------------------------- edge scoring: one warp per edge
__global__ __launch_bounds__(256) void k_score(const int* __restrict__ ei,
                                               float* __restrict__ logits) {
    int gw = (blockIdx.x * blockDim.x + threadIdx.x) >> 5;
    int lane = threadIdx.x & 31;
    if (gw >= N_PRED) return;
    int a = ei[gw];
    int b = ei[N_PRED + gw];
    float4 va = ((const float4*)g_outf)[(size_t)a * 32 + lane];
    float4 vb = ((const float4*)g_outf)[(size_t)b * 32 + lane];
    float p = va.x * vb.x + va.y * vb.y + va.z * vb.z + va.w * vb.w;
    #pragma unroll
    for (int o = 16; o; o >>= 1) p += __shfl_xor_sync(0xFFFFFFFFu, p, o);
    if (lane == 0) logits[gw] = p;
}

// ----------------------------------------------------------------
extern "C" void kernel_launch(void* const* d_in, const int* in_sizes, int n_in,
                              void* d_out, int out_size) {
    const float* x   = (const float*)d_in[0];
    const int*   ei  = (const int*)d_in[1];   // edge_index [2, N_PRED]
    const int*   pos = (const int*)d_in[2];   // pos_edge_index [2, N_POS]
    const float* W1  = (const float*)d_in[3];
    const float* b1  = (const float*)d_in[4];
    const float* Wc  = (const float*)d_in[5];
    const float* bc  = (const float*)d_in[6];
    float* logits = (float*)d_out;

    k_fuse<<<(D_IN * D_OUT + 255) / 256, 256>>>(W1, Wc, b1);        // 1
    k_zero_cnt<<<(N_NODES + 255) / 256, 256>>>();                   // 2
    k_count<<<(N_POS + 255) / 256, 256>>>(pos);                     // 3
    k_scan<<<1, 1024>>>();                                          // 4
    k_fill<<<(N_POS + 255) / 256, 256>>>(pos);                      // 5
    k_gemm<<<(N_NODES + BM - 1) / BM, 256>>>(x);                    // 6 (ncu -s 5 lands here)
    k_aggregate<<<(N_NODES * 32 + 255) / 256, 256>>>(bc);           // 7
    k_score<<<(N_PRED * 32 + 255) / 256, 256>>>(ei, logits);        // 8
}

// round 5
// speedup vs baseline: 1.3182x; 1.2038x over previous
#include <cuda_runtime.h>

#define N_NODES 50000
#define D_IN    256
#define D_OUT   128
#define N_POS   1600000
#define N_PRED  500000
#define SCAN_NBLK ((N_NODES + 1023) / 1024)   // 49

// Scratch (allocation-free rule: device globals)
__device__ float g_W2[D_IN * D_OUT];              // fused weight W1@Wc
__device__ float g_c2[D_OUT];                     // fused bias b1@Wc
__device__ float g_h[(size_t)N_NODES * D_OUT];    // x@W2 + c2
__device__ float g_outf[(size_t)N_NODES * D_OUT]; // aggregated node embeddings
__device__ float g_dinv[N_NODES];
__device__ int   g_cnt[N_NODES];                  // in-degree (excl self loop)
__device__ int   g_off[N_NODES];                  // CSR offsets
__device__ int   g_cursor[N_NODES];               // fill cursors
__device__ int   g_srcs[N_POS];                   // CSR source list
__device__ int   g_part[SCAN_NBLK];               // scan block partials

// ---------------------------------------------------------------- weight fuse
__global__ void k_fuse(const float* __restrict__ W1, const float* __restrict__ Wc,
                       const float* __restrict__ b1) {
    int idx = blockIdx.x * blockDim.x + threadIdx.x;
    if (idx >= D_IN * D_OUT) return;
    int k = idx >> 7, j = idx & 127;
    float acc = 0.f;
    #pragma unroll 8
    for (int m = 0; m < D_IN; ++m)
        acc = fmaf(W1[k * D_IN + m], Wc[m * D_OUT + j], acc);
    g_W2[idx] = acc;
    if (idx < D_OUT) {
        float c = 0.f;
        for (int m = 0; m < D_IN; ++m)
            c = fmaf(b1[m], Wc[m * D_OUT + idx], c);
        g_c2[idx] = c;
    }
}

// ---------------------------------------------------------------- degree count
__global__ void k_zero_cnt() {
    int i = blockIdx.x * blockDim.x + threadIdx.x;
    if (i < N_NODES) g_cnt[i] = 0;
}

__global__ void k_count(const int* __restrict__ pos) {
    int e = blockIdx.x * blockDim.x + threadIdx.x;
    if (e < N_POS) atomicAdd(&g_cnt[pos[N_POS + e]], 1);
}

// ---------------------------------------------------------------- parallel scan, phase 1
// Per-block (1024 threads) exclusive scan of g_cnt chunk -> g_off (chunk-local),
// dinv = rsqrt(cnt+1) on the way, block total -> g_part.
__global__ __launch_bounds__(1024) void k_scan1() {
    __shared__ int warp_sum[32];
    int tid  = threadIdx.x;
    int lane = tid & 31;
    int wid  = tid >> 5;
    int i = blockIdx.x * 1024 + tid;
    int v = (i < N_NODES) ? g_cnt[i] : 0;

    // warp inclusive scan
    int s = v;
    #pragma unroll
    for (int o = 1; o < 32; o <<= 1) {
        int t = __shfl_up_sync(0xFFFFFFFFu, s, o);
        if (lane >= o) s += t;
    }
    if (lane == 31) warp_sum[wid] = s;
    __syncthreads();

    // warp 0 scans the 32 warp sums (exclusive)
    if (wid == 0) {
        int ws = warp_sum[lane];
        int t2 = ws;
        #pragma unroll
        for (int o = 1; o < 32; o <<= 1) {
            int t = __shfl_up_sync(0xFFFFFFFFu, t2, o);
            if (lane >= o) t2 += t;
        }
        warp_sum[lane] = t2 - ws;   // exclusive
        if (lane == 31) g_part[blockIdx.x] = t2;  // block total
    }
    __syncthreads();

    if (i < N_NODES) {
        g_off[i]  = warp_sum[wid] + s - v;        // chunk-local exclusive
        g_dinv[i] = rsqrtf((float)v + 1.0f);
    }
}

// ---------------------------------------------------------------- scan phase 2: tiny serial scan of partials
__global__ void k_scan2() {
    if (threadIdx.x == 0) {
        int run = 0;
        #pragma unroll 7
        for (int b = 0; b < SCAN_NBLK; ++b) {
            int t = g_part[b];
            g_part[b] = run;
            run += t;
        }
    }
}

// ---------------------------------------------------------------- scan phase 3: add block base, init cursor
__global__ void k_scan3() {
    int i = blockIdx.x * blockDim.x + threadIdx.x;
    if (i >= N_NODES) return;
    int o = g_off[i] + g_part[i >> 10];
    g_off[i] = o;
    g_cursor[i] = o;
}

// ---------------------------------------------------------------- CSR fill
__global__ void k_fill(const int* __restrict__ pos) {
    int e = blockIdx.x * blockDim.x + threadIdx.x;
    if (e >= N_POS) return;
    int r = pos[e];
    int c = pos[N_POS + e];
    int p = atomicAdd(&g_cursor[c], 1);
    g_srcs[p] = r;
}

// ---------------------------------------------------------------- GEMM h = x @ W2 + c2
// Tile: BM=64 rows, full N=128, BK=16. 256 threads, each computes 4x8 outputs.
#define BM 64
#define BK 16
__global__ __launch_bounds__(256) void k_gemm(const float* __restrict__ x) {
    __shared__ float sx[BK][BM + 1];   // x tile, transposed (k-major)
    __shared__ float sw[BK][D_OUT];    // W2 tile

    int tid = threadIdx.x;
    int tx = tid & 15;   // col group (0..15) -> 8 cols each
    int ty = tid >> 4;   // row group (0..15) -> 4 rows each
    int row0 = blockIdx.x * BM;

    float acc[4][8];
    #pragma unroll
    for (int i = 0; i < 4; ++i)
        #pragma unroll
        for (int j = 0; j < 8; ++j) acc[i][j] = 0.f;

    int lm = tid >> 2;         // x-load: row within tile (0..63)
    int lk = (tid & 3) * 4;    // x-load: k offset (0,4,8,12)
    int wk = tid >> 5;         // w-load: k row (0..7)
    int wj = (tid & 31) * 4;   // w-load: col offset

    for (int k0 = 0; k0 < D_IN; k0 += BK) {
        int grow = row0 + lm;
        float4 xv = make_float4(0.f, 0.f, 0.f, 0.f);
        if (grow < N_NODES)
            xv = *(const float4*)(x + (size_t)grow * D_IN + k0 + lk);
        sx[lk + 0][lm] = xv.x; sx[lk + 1][lm] = xv.y;
        sx[lk + 2][lm] = xv.z; sx[lk + 3][lm] = xv.w;

        *(float4*)&sw[wk][wj]     = *(const float4*)&g_W2[(k0 + wk) * D_OUT + wj];
        *(float4*)&sw[wk + 8][wj] = *(const float4*)&g_W2[(k0 + wk + 8) * D_OUT + wj];
        __syncthreads();

        #pragma unroll
        for (int kk = 0; kk < BK; ++kk) {
            float aa[4];
            #pragma unroll
            for (int i = 0; i < 4; ++i) aa[i] = sx[kk][ty * 4 + i];
            const float4* swr = (const float4*)&sw[kk][0];
            float4 b0 = swr[tx * 2], b1v = swr[tx * 2 + 1];
            float bb[8] = {b0.x, b0.y, b0.z, b0.w, b1v.x, b1v.y, b1v.z, b1v.w};
            #pragma unroll
            for (int i = 0; i < 4; ++i)
                #pragma unroll
                for (int j = 0; j < 8; ++j)
                    acc[i][j] = fmaf(aa[i], bb[j], acc[i][j]);
        }
        __syncthreads();
    }

    float4 c2a = *(const float4*)&g_c2[tx * 8];
    float4 c2b = *(const float4*)&g_c2[tx * 8 + 4];
    #pragma unroll
    for (int i = 0; i < 4; ++i) {
        int row = row0 + ty * 4 + i;
        if (row >= N_NODES) continue;
        float4 o0 = make_float4(acc[i][0] + c2a.x, acc[i][1] + c2a.y,
                                acc[i][2] + c2a.z, acc[i][3] + c2a.w);
        float4 o1 = make_float4(acc[i][4] + c2b.x, acc[i][5] + c2b.y,
                                acc[i][6] + c2b.z, acc[i][7] + c2b.w);
        *(float4*)&g_h[(size_t)row * D_OUT + tx * 8]     = o0;
        *(float4*)&g_h[(size_t)row * D_OUT + tx * 8 + 4] = o1;
    }
}

// ---------------------------------------------------------------- aggregate: one warp per node (gather)
// out[c] = bc + dinv[c] * ( dinv[c]*h[c] + sum_r dinv[r]*h[r] )
__global__ __launch_bounds__(256) void k_aggregate(const float* __restrict__ bc) {
    int node = (blockIdx.x * blockDim.x + threadIdx.x) >> 5;
    int lane = threadIdx.x & 31;
    if (node >= N_NODES) return;

    float dc = g_dinv[node];
    float4 hv = ((const float4*)g_h)[(size_t)node * 32 + lane];
    float4 acc = make_float4(dc * hv.x, dc * hv.y, dc * hv.z, dc * hv.w);

    int s0 = g_off[node];
    int cnt = g_cnt[node];
    #pragma unroll 2
    for (int j = 0; j < cnt; ++j) {
        int r = g_srcs[s0 + j];            // broadcast load
        float w = g_dinv[r];               // broadcast load
        float4 v = ((const float4*)g_h)[(size_t)r * 32 + lane];
        acc.x = fmaf(w, v.x, acc.x);
        acc.y = fmaf(w, v.y, acc.y);
        acc.z = fmaf(w, v.z, acc.z);
        acc.w = fmaf(w, v.w, acc.w);
    }

    float4 bv = ((const float4*)bc)[lane];
    float4 o = make_float4(fmaf(dc, acc.x, bv.x), fmaf(dc, acc.y, bv.y),
                           fmaf(dc, acc.z, bv.z), fmaf(dc, acc.w, bv.w));
    ((float4*)g_outf)[(size_t)node * 32 + lane] = o;
}

// ---------------------------------------------------------------- edge scoring: one warp per edge
__global__ __launch_bounds__(256) void k_score(const int* __restrict__ ei,
                                               float* __restrict__ logits) {
    int gw = (blockIdx.x * blockDim.x + threadIdx.x) >> 5;
    int lane = threadIdx.x & 31;
    if (gw >= N_PRED) return;
    int a = ei[gw];
    int b = ei[N_PRED + gw];
    float4 va = ((const float4*)g_outf)[(size_t)a * 32 + lane];
    float4 vb = ((const float4*)g_outf)[(size_t)b * 32 + lane];
    float p = va.x * vb.x + va.y * vb.y + va.z * vb.z + va.w * vb.w;
    #pragma unroll
    for (int o = 16; o; o >>= 1) p += __shfl_xor_sync(0xFFFFFFFFu, p, o);
    if (lane == 0) logits[gw] = p;
}

// ----------------------------------------------------------------
extern "C" void kernel_launch(void* const* d_in, const int* in_sizes, int n_in,
                              void* d_out, int out_size) {
    const float* x   = (const float*)d_in[0];
    const int*   ei  = (const int*)d_in[1];   // edge_index [2, N_PRED]
    const int*   pos = (const int*)d_in[2];   // pos_edge_index [2, N_POS]
    const float* W1  = (const float*)d_in[3];
    const float* b1  = (const float*)d_in[4];
    const float* Wc  = (const float*)d_in[5];
    const float* bc  = (const float*)d_in[6];
    float* logits = (float*)d_out;

    k_fuse<<<(D_IN * D_OUT + 255) / 256, 256>>>(W1, Wc, b1);        // 1
    k_zero_cnt<<<(N_NODES + 255) / 256, 256>>>();                   // 2
    k_count<<<(N_POS + 255) / 256, 256>>>(pos);                     // 3
    k_scan1<<<SCAN_NBLK, 1024>>>();                                 // 4
    k_scan2<<<1, 32>>>();                                           // 5
    k_scan3<<<(N_NODES + 255) / 256, 256>>>();                      // 6 (ncu -s 5 lands here)
    k_fill<<<(N_POS + 255) / 256, 256>>>(pos);                      // 7
    k_gemm<<<(N_NODES + BM - 1) / BM, 256>>>(x);                    // 8
    k_aggregate<<<(N_NODES * 32 + 255) / 256, 256>>>(bc);           // 9
    k_score<<<(N_PRED * 32 + 255) / 256, 256>>>(ei, logits);        // 10
}

// round 8
// speedup vs baseline: 1.6739x; 1.2698x over previous
#include <cuda_runtime.h>
#include <cuda_bf16.h>
#include <mma.h>
#include <cstdint>

using namespace nvcuda;

#define N_NODES 50000
#define D_IN    256
#define D_OUT   128
#define N_POS   1600000
#define N_PRED  500000
#define SCAN_NBLK ((N_NODES + 1023) / 1024)   // 49

// ---- GEMM tiling ----
#define BMT 128                                  // rows per CTA
#define NBLK_GEMM ((N_NODES + BMT - 1) / BMT)    // 391
#define N_ROWS_PAD (NBLK_GEMM * BMT)             // 50048 (unguarded wmma stores)
#define BPAD 136                                 // smem B stride (bf16 elems)
#define APAD 40                                  // smem A stride (bf16 elems)
// dynamic smem: Bh + Bl + Ah + Al + bias tile
#define SMEM_TOTAL (2 * 256 * BPAD * 2 + 2 * 128 * APAD * 2 + 16 * BPAD * 4)  // 168448

// Scratch (allocation-free rule: device globals)
__device__ float g_W2[D_IN * D_OUT];              // fused weight W1@Wc (f32)
__device__ float g_c2[D_OUT];                     // fused bias b1@Wc
__device__ __nv_bfloat16 g_Wh[D_IN * D_OUT];      // bf16 hi part of W2 [k][n]
__device__ __nv_bfloat16 g_Wl[D_IN * D_OUT];      // bf16 lo part of W2 [k][n]
__device__ float g_h[(size_t)N_ROWS_PAD * D_OUT]; // x@W2 + c2 (padded rows)
__device__ float g_outf[(size_t)N_NODES * D_OUT]; // aggregated node embeddings
__device__ float g_dinv[N_NODES];
__device__ int   g_cnt[N_NODES];
__device__ int   g_off[N_NODES];
__device__ int   g_cursor[N_NODES];
__device__ int   g_srcs[N_POS];
__device__ int   g_part[SCAN_NBLK];

// ---------------------------------------------------------------- weight fuse
__global__ void k_fuse(const float* __restrict__ W1, const float* __restrict__ Wc,
                       const float* __restrict__ b1) {
    int idx = blockIdx.x * blockDim.x + threadIdx.x;
    if (idx >= D_IN * D_OUT) return;
    int k = idx >> 7, j = idx & 127;
    float acc = 0.f;
    #pragma unroll 8
    for (int m = 0; m < D_IN; ++m)
        acc = fmaf(W1[k * D_IN + m], Wc[m * D_OUT + j], acc);
    g_W2[idx] = acc;
    if (idx < D_OUT) {
        float c = 0.f;
        for (int m = 0; m < D_IN; ++m)
            c = fmaf(b1[m], Wc[m * D_OUT + idx], c);
        g_c2[idx] = c;
    }
}

// ---------------------------------------------------------------- pack W hi/lo bf16
__global__ void k_pack() {
    int i = blockIdx.x * blockDim.x + threadIdx.x;
    if (i >= D_IN * D_OUT) return;
    float w = g_W2[i];
    __nv_bfloat16 h = __float2bfloat16_rn(w);
    g_Wh[i] = h;
    g_Wl[i] = __float2bfloat16_rn(w - __bfloat162float(h));
}

// ---------------------------------------------------------------- degree count
__global__ void k_zero_cnt() {
    int i = blockIdx.x * blockDim.x + threadIdx.x;
    if (i < N_NODES) g_cnt[i] = 0;
}

__global__ void k_count(const int* __restrict__ pos) {
    int e = blockIdx.x * blockDim.x + threadIdx.x;
    if (e < N_POS) atomicAdd(&g_cnt[pos[N_POS + e]], 1);
}

// ---------------------------------------------------------------- parallel scan
__global__ __launch_bounds__(1024) void k_scan1() {
    __shared__ int warp_sum[32];
    int tid  = threadIdx.x;
    int lane = tid & 31;
    int wid  = tid >> 5;
    int i = blockIdx.x * 1024 + tid;
    int v = (i < N_NODES) ? g_cnt[i] : 0;
    int s = v;
    #pragma unroll
    for (int o = 1; o < 32; o <<= 1) {
        int t = __shfl_up_sync(0xFFFFFFFFu, s, o);
        if (lane >= o) s += t;
    }
    if (lane == 31) warp_sum[wid] = s;
    __syncthreads();
    if (wid == 0) {
        int ws = warp_sum[lane];
        int t2 = ws;
        #pragma unroll
        for (int o = 1; o < 32; o <<= 1) {
            int t = __shfl_up_sync(0xFFFFFFFFu, t2, o);
            if (lane >= o) t2 += t;
        }
        warp_sum[lane] = t2 - ws;
        if (lane == 31) g_part[blockIdx.x] = t2;
    }
    __syncthreads();
    if (i < N_NODES) {
        g_off[i]  = warp_sum[wid] + s - v;
        g_dinv[i] = rsqrtf((float)v + 1.0f);
    }
}

__global__ void k_scan2() {
    if (threadIdx.x == 0) {
        int run = 0;
        #pragma unroll 7
        for (int b = 0; b < SCAN_NBLK; ++b) {
            int t = g_part[b];
            g_part[b] = run;
            run += t;
        }
    }
}

__global__ void k_scan3() {
    int i = blockIdx.x * blockDim.x + threadIdx.x;
    if (i >= N_NODES) return;
    int o = g_off[i] + g_part[i >> 10];
    g_off[i] = o;
    g_cursor[i] = o;
}

// ---------------------------------------------------------------- CSR fill
__global__ void k_fill(const int* __restrict__ pos) {
    int e = blockIdx.x * blockDim.x + threadIdx.x;
    if (e >= N_POS) return;
    int r = pos[e];
    int c = pos[N_POS + e];
    int p = atomicAdd(&g_cursor[c], 1);
    g_srcs[p] = r;
}

// ---------------------------------------------------------------- tensor-core GEMM (wmma bf16 hi/lo split)
// h = x @ W2 + c2 ; error: dropped xl*Wl term ~2^-16 relative.
__global__ __launch_bounds__(256) void k_gemm_tc(const float* __restrict__ x) {
    extern __shared__ char smem[];
    __nv_bfloat16* sBh = (__nv_bfloat16*)smem;           // [256][BPAD]
    __nv_bfloat16* sBl = sBh + 256 * BPAD;               // [256][BPAD]
    __nv_bfloat16* sAh = sBl + 256 * BPAD;               // [128][APAD]
    __nv_bfloat16* sAl = sAh + 128 * APAD;               // [128][APAD]
    float*         sBias = (float*)(sAl + 128 * APAD);   // [16][BPAD]

    int tid = threadIdx.x;
    int wid = tid >> 5;
    int warp_m = wid >> 2;        // 0..1 (64 rows each)
    int warp_n = wid & 3;         // 0..3 (32 cols each)
    int row0 = blockIdx.x * BMT;

    // load B (both hi and lo) into padded smem, 8 bf16 per uint4
    {
        const uint4* srcH = (const uint4*)g_Wh;
        const uint4* srcL = (const uint4*)g_Wl;
        #pragma unroll 4
        for (int i = tid; i < 256 * 16; i += 256) {
            int r = i >> 4, c8 = i & 15;
            *(uint4*)&sBh[r * BPAD + c8 * 8] = srcH[i];
            *(uint4*)&sBl[r * BPAD + c8 * 8] = srcL[i];
        }
        for (int i = tid; i < 16 * 128; i += 256) {
            int r = i >> 7, c = i & 127;
            sBias[r * BPAD + c] = g_c2[c];
        }
    }
    __syncthreads();

    // accumulators initialized from replicated bias rows (folds +c2 into MMA)
    wmma::fragment<wmma::accumulator, 16, 16, 16, float> acc[4][2];
    #pragma unroll
    for (int m = 0; m < 4; ++m)
        #pragma unroll
        for (int n = 0; n < 2; ++n)
            wmma::load_matrix_sync(acc[m][n], sBias + warp_n * 32 + n * 16, BPAD,
                                   wmma::mem_row_major);

    for (int k0 = 0; k0 < D_IN; k0 += 32) {
        // cooperative load+convert x[row0:+128, k0:+32] -> sAh/sAl
        {
            int r = tid >> 1;
            int h16 = (tid & 1) * 16;
            int grow = row0 + r;
            float v[16];
            if (grow < N_NODES) {
                const float4* p = (const float4*)(x + (size_t)grow * D_IN + k0 + h16);
                #pragma unroll
                for (int q = 0; q < 4; ++q) {
                    float4 f = p[q];
                    v[4 * q + 0] = f.x; v[4 * q + 1] = f.y;
                    v[4 * q + 2] = f.z; v[4 * q + 3] = f.w;
                }
            } else {
                #pragma unroll
                for (int q = 0; q < 16; ++q) v[q] = 0.f;
            }
            uint32_t hp[8], lp[8];
            #pragma unroll
            for (int q = 0; q < 8; ++q) {
                __nv_bfloat16 h0 = __float2bfloat16_rn(v[2 * q]);
                __nv_bfloat16 h1 = __float2bfloat16_rn(v[2 * q + 1]);
                __nv_bfloat16 l0 = __float2bfloat16_rn(v[2 * q] - __bfloat162float(h0));
                __nv_bfloat16 l1 = __float2bfloat16_rn(v[2 * q + 1] - __bfloat162float(h1));
                hp[q] = (uint32_t)__bfloat16_as_ushort(h0) | ((uint32_t)__bfloat16_as_ushort(h1) << 16);
                lp[q] = (uint32_t)__bfloat16_as_ushort(l0) | ((uint32_t)__bfloat16_as_ushort(l1) << 16);
            }
            uint4* dh = (uint4*)&sAh[r * APAD + h16];
            uint4* dl = (uint4*)&sAl[r * APAD + h16];
            dh[0] = make_uint4(hp[0], hp[1], hp[2], hp[3]);
            dh[1] = make_uint4(hp[4], hp[5], hp[6], hp[7]);
            dl[0] = make_uint4(lp[0], lp[1], lp[2], lp[3]);
            dl[1] = make_uint4(lp[4], lp[5], lp[6], lp[7]);
        }
        __syncthreads();

        #pragma unroll
        for (int kk = 0; kk < 32; kk += 16) {
            wmma::fragment<wmma::matrix_a, 16, 16, 16, __nv_bfloat16, wmma::row_major> ah[4], al[4];
            wmma::fragment<wmma::matrix_b, 16, 16, 16, __nv_bfloat16, wmma::row_major> bh[2], bl[2];
            #pragma unroll
            for (int m = 0; m < 4; ++m) {
                int ar = warp_m * 64 + m * 16;
                wmma::load_matrix_sync(ah[m], &sAh[ar * APAD + kk], APAD);
                wmma::load_matrix_sync(al[m], &sAl[ar * APAD + kk], APAD);
            }
            #pragma unroll
            for (int n = 0; n < 2; ++n) {
                int bc = warp_n * 32 + n * 16;
                wmma::load_matrix_sync(bh[n], &sBh[(k0 + kk) * BPAD + bc], BPAD);
                wmma::load_matrix_sync(bl[n], &sBl[(k0 + kk) * BPAD + bc], BPAD);
            }
            #pragma unroll
            for (int m = 0; m < 4; ++m)
                #pragma unroll
                for (int n = 0; n < 2; ++n) {
                    wmma::mma_sync(acc[m][n], ah[m], bh[n], acc[m][n]);
                    wmma::mma_sync(acc[m][n], ah[m], bl[n], acc[m][n]);
                    wmma::mma_sync(acc[m][n], al[m], bh[n], acc[m][n]);
                }
        }
        __syncthreads();
    }

    // store directly (g_h is padded to 50048 rows -> no guards)
    #pragma unroll
    for (int m = 0; m < 4; ++m) {
        int row = row0 + warp_m * 64 + m * 16;
        #pragma unroll
        for (int n = 0; n < 2; ++n) {
            int col = warp_n * 32 + n * 16;
            wmma::store_matrix_sync(g_h + (size_t)row * D_OUT + col, acc[m][n],
                                    D_OUT, wmma::mem_row_major);
        }
    }
}

// ---------------------------------------------------------------- aggregate: one warp per node
// out[c] = bc + dinv[c] * ( dinv[c]*h[c] + sum_r dinv[r]*h[r] )
__global__ __launch_bounds__(256) void k_aggregate(const float* __restrict__ bc) {
    int node = (blockIdx.x * blockDim.x + threadIdx.x) >> 5;
    int lane = threadIdx.x & 31;
    if (node >= N_NODES) return;

    float dc = g_dinv[node];
    float4 hv = ((const float4*)g_h)[(size_t)node * 32 + lane];
    float4 acc = make_float4(dc * hv.x, dc * hv.y, dc * hv.z, dc * hv.w);

    int s0 = g_off[node];
    int cnt = g_cnt[node];
    #pragma unroll 2
    for (int j = 0; j < cnt; ++j) {
        int r = g_srcs[s0 + j];
        float w = g_dinv[r];
        float4 v = ((const float4*)g_h)[(size_t)r * 32 + lane];
        acc.x = fmaf(w, v.x, acc.x);
        acc.y = fmaf(w, v.y, acc.y);
        acc.z = fmaf(w, v.z, acc.z);
        acc.w = fmaf(w, v.w, acc.w);
    }

    float4 bv = ((const float4*)bc)[lane];
    float4 o = make_float4(fmaf(dc, acc.x, bv.x), fmaf(dc, acc.y, bv.y),
                           fmaf(dc, acc.z, bv.z), fmaf(dc, acc.w, bv.w));
    ((float4*)g_outf)[(size_t)node * 32 + lane] = o;
}

// ---------------------------------------------------------------- edge scoring
__global__ __launch_bounds__(256) void k_score(const int* __restrict__ ei,
                                               float* __restrict__ logits) {
    int gw = (blockIdx.x * blockDim.x + threadIdx.x) >> 5;
    int lane = threadIdx.x & 31;
    if (gw >= N_PRED) return;
    int a = ei[gw];
    int b = ei[N_PRED + gw];
    float4 va = ((const float4*)g_outf)[(size_t)a * 32 + lane];
    float4 vb = ((const float4*)g_outf)[(size_t)b * 32 + lane];
    float p = va.x * vb.x + va.y * vb.y + va.z * vb.z + va.w * vb.w;
    #pragma unroll
    for (int o = 16; o; o >>= 1) p += __shfl_xor_sync(0xFFFFFFFFu, p, o);
    if (lane == 0) logits[gw] = p;
}

// ----------------------------------------------------------------
extern "C" void kernel_launch(void* const* d_in, const int* in_sizes, int n_in,
                              void* d_out, int out_size) {
    const float* x   = (const float*)d_in[0];
    const int*   ei  = (const int*)d_in[1];
    const int*   pos = (const int*)d_in[2];
    const float* W1  = (const float*)d_in[3];
    const float* b1  = (const float*)d_in[4];
    const float* Wc  = (const float*)d_in[5];
    const float* bc  = (const float*)d_in[6];
    float* logits = (float*)d_out;

    static_assert(SMEM_TOTAL <= 227 * 1024, "smem budget");
    cudaFuncSetAttribute(k_gemm_tc, cudaFuncAttributeMaxDynamicSharedMemorySize, SMEM_TOTAL);

    k_fuse<<<(D_IN * D_OUT + 255) / 256, 256>>>(W1, Wc, b1);        // 1
    k_pack<<<(D_IN * D_OUT + 255) / 256, 256>>>();                  // 2
    k_zero_cnt<<<(N_NODES + 255) / 256, 256>>>();                   // 3
    k_count<<<(N_POS + 255) / 256, 256>>>(pos);                     // 4
    k_scan1<<<SCAN_NBLK, 1024>>>();                                 // 5
    k_gemm_tc<<<NBLK_GEMM, 256, SMEM_TOTAL>>>(x);                   // 6 (ncu -s 5 lands here)
    k_scan2<<<1, 32>>>();                                           // 7
    k_scan3<<<(N_NODES + 255) / 256, 256>>>();                      // 8
    k_fill<<<(N_POS + 255) / 256, 256>>>(pos);                      // 9
    k_aggregate<<<(N_NODES * 32 + 255) / 256, 256>>>(bc);           // 10
    k_score<<<(N_PRED * 32 + 255) / 256, 256>>>(ei, logits);        // 11
}

// round 9
// speedup vs baseline: 1.8117x; 1.0824x over previous
#include <cuda_runtime.h>
#include <cuda_bf16.h>
#include <mma.h>
#include <cstdint>

using namespace nvcuda;

#define N_NODES 50000
#define D_IN    256
#define D_OUT   128
#define N_POS   1600000
#define N_PRED  500000
#define SCAN_NBLK ((N_NODES + 1023) / 1024)   // 49

// ---- GEMM tiling ----
#define BMT 128                                  // rows per CTA
#define NBLK_GEMM ((N_NODES + BMT - 1) / BMT)    // 391
#define N_ROWS_PAD (NBLK_GEMM * BMT)             // 50048 (unguarded wmma stores)
#define BPAD 136                                 // smem B stride (bf16 elems)
#define APAD 40                                  // smem A stride (bf16 elems)
// dynamic smem: Bh + Bl + Ah + Al + bias tile
#define SMEM_TOTAL (2 * 256 * BPAD * 2 + 2 * 128 * APAD * 2 + 16 * BPAD * 4)  // 168448

// Scratch (allocation-free rule: device globals)
__device__ float g_W2[D_IN * D_OUT];              // fused weight W1@Wc (f32)
__device__ float g_c2[D_OUT];                     // fused bias b1@Wc
__device__ __nv_bfloat16 g_Wh[D_IN * D_OUT];      // bf16 hi part of W2 [k][n]
__device__ __nv_bfloat16 g_Wl[D_IN * D_OUT];      // bf16 lo part of W2 [k][n]
__device__ float g_h[(size_t)N_ROWS_PAD * D_OUT]; // x@W2 + c2 (padded rows)
__device__ float g_outf[(size_t)N_NODES * D_OUT]; // aggregated node embeddings
__device__ float g_dinv[N_NODES];
__device__ int   g_cnt[N_NODES];
__device__ int   g_off[N_NODES];
__device__ int   g_cursor[N_NODES];
__device__ int   g_srcs[N_POS];
__device__ int   g_part[SCAN_NBLK];

// ---------------------------------------------------------------- weight fuse
__global__ void k_fuse(const float* __restrict__ W1, const float* __restrict__ Wc,
                       const float* __restrict__ b1) {
    int idx = blockIdx.x * blockDim.x + threadIdx.x;
    if (idx >= D_IN * D_OUT) return;
    int k = idx >> 7, j = idx & 127;
    float acc = 0.f;
    #pragma unroll 8
    for (int m = 0; m < D_IN; ++m)
        acc = fmaf(W1[k * D_IN + m], Wc[m * D_OUT + j], acc);
    g_W2[idx] = acc;
    if (idx < D_OUT) {
        float c = 0.f;
        for (int m = 0; m < D_IN; ++m)
            c = fmaf(b1[m], Wc[m * D_OUT + idx], c);
        g_c2[idx] = c;
    }
}

// ---------------------------------------------------------------- pack W hi/lo bf16
__global__ void k_pack() {
    int i = blockIdx.x * blockDim.x + threadIdx.x;
    if (i >= D_IN * D_OUT) return;
    float w = g_W2[i];
    __nv_bfloat16 h = __float2bfloat16_rn(w);
    g_Wh[i] = h;
    g_Wl[i] = __float2bfloat16_rn(w - __bfloat162float(h));
}

// ---------------------------------------------------------------- degree count
__global__ void k_zero_cnt() {
    int i = blockIdx.x * blockDim.x + threadIdx.x;
    if (i < N_NODES) g_cnt[i] = 0;
}

__global__ void k_count(const int* __restrict__ pos) {
    int e = blockIdx.x * blockDim.x + threadIdx.x;
    if (e < N_POS) atomicAdd(&g_cnt[pos[N_POS + e]], 1);
}

// ---------------------------------------------------------------- parallel scan
__global__ __launch_bounds__(1024) void k_scan1() {
    __shared__ int warp_sum[32];
    int tid  = threadIdx.x;
    int lane = tid & 31;
    int wid  = tid >> 5;
    int i = blockIdx.x * 1024 + tid;
    int v = (i < N_NODES) ? g_cnt[i] : 0;
    int s = v;
    #pragma unroll
    for (int o = 1; o < 32; o <<= 1) {
        int t = __shfl_up_sync(0xFFFFFFFFu, s, o);
        if (lane >= o) s += t;
    }
    if (lane == 31) warp_sum[wid] = s;
    __syncthreads();
    if (wid == 0) {
        int ws = warp_sum[lane];
        int t2 = ws;
        #pragma unroll
        for (int o = 1; o < 32; o <<= 1) {
            int t = __shfl_up_sync(0xFFFFFFFFu, t2, o);
            if (lane >= o) t2 += t;
        }
        warp_sum[lane] = t2 - ws;
        if (lane == 31) g_part[blockIdx.x] = t2;
    }
    __syncthreads();
    if (i < N_NODES) {
        g_off[i]  = warp_sum[wid] + s - v;
        g_dinv[i] = rsqrtf((float)v + 1.0f);
    }
}

// scan phase 2+3 fused: each thread sums chunk partials (<=48 L2-broadcast ints)
__global__ void k_scan3() {
    int i = blockIdx.x * blockDim.x + threadIdx.x;
    if (i >= N_NODES) return;
    int chunk = i >> 10;
    int base = 0;
    for (int b = 0; b < chunk; ++b) base += g_part[b];
    int o = g_off[i] + base;
    g_off[i] = o;
    g_cursor[i] = o;
}

// ---------------------------------------------------------------- CSR fill
__global__ void k_fill(const int* __restrict__ pos) {
    int e = blockIdx.x * blockDim.x + threadIdx.x;
    if (e >= N_POS) return;
    int r = pos[e];
    int c = pos[N_POS + e];
    int p = atomicAdd(&g_cursor[c], 1);
    g_srcs[p] = r;
}

// ---------------------------------------------------------------- tensor-core GEMM (wmma bf16 hi/lo split)
// h = x @ W2 + c2 ; error: dropped xl*Wl term ~2^-16 relative.
__global__ __launch_bounds__(256) void k_gemm_tc(const float* __restrict__ x) {
    extern __shared__ char smem[];
    __nv_bfloat16* sBh = (__nv_bfloat16*)smem;           // [256][BPAD]
    __nv_bfloat16* sBl = sBh + 256 * BPAD;               // [256][BPAD]
    __nv_bfloat16* sAh = sBl + 256 * BPAD;               // [128][APAD]
    __nv_bfloat16* sAl = sAh + 128 * APAD;               // [128][APAD]
    float*         sBias = (float*)(sAl + 128 * APAD);   // [16][BPAD]

    int tid = threadIdx.x;
    int wid = tid >> 5;
    int warp_m = wid >> 2;        // 0..1 (64 rows each)
    int warp_n = wid & 3;         // 0..3 (32 cols each)
    int row0 = blockIdx.x * BMT;

    // load B (both hi and lo) into padded smem, 8 bf16 per uint4
    {
        const uint4* srcH = (const uint4*)g_Wh;
        const uint4* srcL = (const uint4*)g_Wl;
        #pragma unroll 4
        for (int i = tid; i < 256 * 16; i += 256) {
            int r = i >> 4, c8 = i & 15;
            *(uint4*)&sBh[r * BPAD + c8 * 8] = srcH[i];
            *(uint4*)&sBl[r * BPAD + c8 * 8] = srcL[i];
        }
        for (int i = tid; i < 16 * 128; i += 256) {
            int r = i >> 7, c = i & 127;
            sBias[r * BPAD + c] = g_c2[c];
        }
    }
    __syncthreads();

    // accumulators initialized from replicated bias rows (folds +c2 into MMA)
    wmma::fragment<wmma::accumulator, 16, 16, 16, float> acc[4][2];
    #pragma unroll
    for (int m = 0; m < 4; ++m)
        #pragma unroll
        for (int n = 0; n < 2; ++n)
            wmma::load_matrix_sync(acc[m][n], sBias + warp_n * 32 + n * 16, BPAD,
                                   wmma::mem_row_major);

    for (int k0 = 0; k0 < D_IN; k0 += 32) {
        // cooperative load+convert x[row0:+128, k0:+32] -> sAh/sAl
        {
            int r = tid >> 1;
            int h16 = (tid & 1) * 16;
            int grow = row0 + r;
            float v[16];
            if (grow < N_NODES) {
                const float4* p = (const float4*)(x + (size_t)grow * D_IN + k0 + h16);
                #pragma unroll
                for (int q = 0; q < 4; ++q) {
                    float4 f = p[q];
                    v[4 * q + 0] = f.x; v[4 * q + 1] = f.y;
                    v[4 * q + 2] = f.z; v[4 * q + 3] = f.w;
                }
            } else {
                #pragma unroll
                for (int q = 0; q < 16; ++q) v[q] = 0.f;
            }
            uint32_t hp[8], lp[8];
            #pragma unroll
            for (int q = 0; q < 8; ++q) {
                __nv_bfloat16 h0 = __float2bfloat16_rn(v[2 * q]);
                __nv_bfloat16 h1 = __float2bfloat16_rn(v[2 * q + 1]);
                __nv_bfloat16 l0 = __float2bfloat16_rn(v[2 * q] - __bfloat162float(h0));
                __nv_bfloat16 l1 = __float2bfloat16_rn(v[2 * q + 1] - __bfloat162float(h1));
                hp[q] = (uint32_t)__bfloat16_as_ushort(h0) | ((uint32_t)__bfloat16_as_ushort(h1) << 16);
                lp[q] = (uint32_t)__bfloat16_as_ushort(l0) | ((uint32_t)__bfloat16_as_ushort(l1) << 16);
            }
            uint4* dh = (uint4*)&sAh[r * APAD + h16];
            uint4* dl = (uint4*)&sAl[r * APAD + h16];
            dh[0] = make_uint4(hp[0], hp[1], hp[2], hp[3]);
            dh[1] = make_uint4(hp[4], hp[5], hp[6], hp[7]);
            dl[0] = make_uint4(lp[0], lp[1], lp[2], lp[3]);
            dl[1] = make_uint4(lp[4], lp[5], lp[6], lp[7]);
        }
        __syncthreads();

        #pragma unroll
        for (int kk = 0; kk < 32; kk += 16) {
            wmma::fragment<wmma::matrix_a, 16, 16, 16, __nv_bfloat16, wmma::row_major> ah[4], al[4];
            wmma::fragment<wmma::matrix_b, 16, 16, 16, __nv_bfloat16, wmma::row_major> bh[2], bl[2];
            #pragma unroll
            for (int m = 0; m < 4; ++m) {
                int ar = warp_m * 64 + m * 16;
                wmma::load_matrix_sync(ah[m], &sAh[ar * APAD + kk], APAD);
                wmma::load_matrix_sync(al[m], &sAl[ar * APAD + kk], APAD);
            }
            #pragma unroll
            for (int n = 0; n < 2; ++n) {
                int bc = warp_n * 32 + n * 16;
                wmma::load_matrix_sync(bh[n], &sBh[(k0 + kk) * BPAD + bc], BPAD);
                wmma::load_matrix_sync(bl[n], &sBl[(k0 + kk) * BPAD + bc], BPAD);
            }
            #pragma unroll
            for (int m = 0; m < 4; ++m)
                #pragma unroll
                for (int n = 0; n < 2; ++n) {
                    wmma::mma_sync(acc[m][n], ah[m], bh[n], acc[m][n]);
                    wmma::mma_sync(acc[m][n], ah[m], bl[n], acc[m][n]);
                    wmma::mma_sync(acc[m][n], al[m], bh[n], acc[m][n]);
                }
        }
        __syncthreads();
    }

    // store directly (g_h is padded to 50048 rows -> no guards)
    #pragma unroll
    for (int m = 0; m < 4; ++m) {
        int row = row0 + warp_m * 64 + m * 16;
        #pragma unroll
        for (int n = 0; n < 2; ++n) {
            int col = warp_n * 32 + n * 16;
            wmma::store_matrix_sync(g_h + (size_t)row * D_OUT + col, acc[m][n],
                                    D_OUT, wmma::mem_row_major);
        }
    }
}

// ---------------------------------------------------------------- aggregate: one warp per node
// out[c] = bc + dinv[c] * ( dinv[c]*h[c] + sum_r dinv[r]*h[r] )
__global__ __launch_bounds__(256) void k_aggregate(const float* __restrict__ bc) {
    int node = (blockIdx.x * blockDim.x + threadIdx.x) >> 5;
    int lane = threadIdx.x & 31;
    if (node >= N_NODES) return;

    float dc = g_dinv[node];
    float4 hv = ((const float4*)g_h)[(size_t)node * 32 + lane];
    float4 acc = make_float4(dc * hv.x, dc * hv.y, dc * hv.z, dc * hv.w);

    int s0 = g_off[node];
    int cnt = g_cnt[node];
    #pragma unroll 2
    for (int j = 0; j < cnt; ++j) {
        int r = g_srcs[s0 + j];
        float w = g_dinv[r];
        float4 v = ((const float4*)g_h)[(size_t)r * 32 + lane];
        acc.x = fmaf(w, v.x, acc.x);
        acc.y = fmaf(w, v.y, acc.y);
        acc.z = fmaf(w, v.z, acc.z);
        acc.w = fmaf(w, v.w, acc.w);
    }

    float4 bv = ((const float4*)bc)[lane];
    float4 o = make_float4(fmaf(dc, acc.x, bv.x), fmaf(dc, acc.y, bv.y),
                           fmaf(dc, acc.z, bv.z), fmaf(dc, acc.w, bv.w));
    ((float4*)g_outf)[(size_t)node * 32 + lane] = o;
}

// ---------------------------------------------------------------- edge scoring
__global__ __launch_bounds__(256) void k_score(const int* __restrict__ ei,
                                               float* __restrict__ logits) {
    int gw = (blockIdx.x * blockDim.x + threadIdx.x) >> 5;
    int lane = threadIdx.x & 31;
    if (gw >= N_PRED) return;
    int a = ei[gw];
    int b = ei[N_PRED + gw];
    float4 va = ((const float4*)g_outf)[(size_t)a * 32 + lane];
    float4 vb = ((const float4*)g_outf)[(size_t)b * 32 + lane];
    float p = va.x * vb.x + va.y * vb.y + va.z * vb.z + va.w * vb.w;
    #pragma unroll
    for (int o = 16; o; o >>= 1) p += __shfl_xor_sync(0xFFFFFFFFu, p, o);
    if (lane == 0) logits[gw] = p;
}

// ----------------------------------------------------------------
extern "C" void kernel_launch(void* const* d_in, const int* in_sizes, int n_in,
                              void* d_out, int out_size) {
    const float* x   = (const float*)d_in[0];
    const int*   ei  = (const int*)d_in[1];
    const int*   pos = (const int*)d_in[2];
    const float* W1  = (const float*)d_in[3];
    const float* b1  = (const float*)d_in[4];
    const float* Wc  = (const float*)d_in[5];
    const float* bc  = (const float*)d_in[6];
    float* logits = (float*)d_out;

    static_assert(SMEM_TOTAL <= 227 * 1024, "smem budget");
    cudaFuncSetAttribute(k_gemm_tc, cudaFuncAttributeMaxDynamicSharedMemorySize, SMEM_TOTAL);

    // Fork a non-blocking side stream so the CSR build (atomic/L2-bound)
    // overlaps the GEMM chain (tensor/smem-bound). Graph capture turns this
    // into parallel branches via the event fork/join.
    cudaStream_t s2;
    cudaEvent_t eFork, eJoin;
    cudaStreamCreateWithFlags(&s2, cudaStreamNonBlocking);
    cudaEventCreateWithFlags(&eFork, cudaEventDisableTiming);
    cudaEventCreateWithFlags(&eJoin, cudaEventDisableTiming);

    cudaEventRecord(eFork, 0);
    cudaStreamWaitEvent(s2, eFork, 0);

    // main stream: GEMM chain
    k_fuse<<<(D_IN * D_OUT + 255) / 256, 256>>>(W1, Wc, b1);
    k_pack<<<(D_IN * D_OUT + 255) / 256, 256>>>();
    k_gemm_tc<<<NBLK_GEMM, 256, SMEM_TOTAL>>>(x);

    // side stream: CSR chain
    k_zero_cnt<<<(N_NODES + 255) / 256, 256, 0, s2>>>();
    k_count<<<(N_POS + 255) / 256, 256, 0, s2>>>(pos);
    k_scan1<<<SCAN_NBLK, 1024, 0, s2>>>();
    k_scan3<<<(N_NODES + 255) / 256, 256, 0, s2>>>();
    k_fill<<<(N_POS + 255) / 256, 256, 0, s2>>>(pos);
    cudaEventRecord(eJoin, s2);
    cudaStreamWaitEvent(0, eJoin, 0);

    // tail (needs both branches)
    k_aggregate<<<(N_NODES * 32 + 255) / 256, 256>>>(bc);
    k_score<<<(N_PRED * 32 + 255) / 256, 256>>>(ei, logits);

    // Destroy handles only when not capturing (destroying a forked stream
    // mid-capture invalidates the graph). The capture call leaks one
    // stream + two events, once.
    cudaStreamCaptureStatus st = cudaStreamCaptureStatusNone;
    cudaStreamIsCapturing((cudaStream_t)0, &st);
    if (st == cudaStreamCaptureStatusNone) {
        cudaStreamDestroy(s2);
        cudaEventDestroy(eFork);
        cudaEventDestroy(eJoin);
    }
}

// round 10
// speedup vs baseline: 1.8130x; 1.0007x over previous
#include <cuda_runtime.h>
#include <cuda_bf16.h>
#include <mma.h>
#include <cstdint>

using namespace nvcuda;

#define N_NODES 50000
#define D_IN    256
#define D_OUT   128
#define N_POS   1600000
#define N_PRED  500000
#define SCAN_NBLK ((N_NODES + 1023) / 1024)   // 49

// ---- GEMM tiling ----
#define BMT 128                                  // rows per CTA
#define NBLK_GEMM ((N_NODES + BMT - 1) / BMT)    // 391
#define N_ROWS_PAD (NBLK_GEMM * BMT)             // 50048 (unguarded wmma stores)
#define BPAD 136                                 // smem B stride (bf16 elems)
#define APAD 40                                  // smem A stride (bf16 elems; 80B = 16B-aligned rows)
// dynamic smem: Bh + Bl + 4 A images (2 buf x hi/lo) + bias tile
#define SMEM_TOTAL (2 * 256 * BPAD * 2 + 4 * 128 * APAD * 2 + 16 * BPAD * 4)  // 188928

// Scratch (allocation-free rule: device globals)
__device__ float g_c2[D_OUT];                     // fused bias b1@Wc
__device__ __nv_bfloat16 g_Wh[D_IN * D_OUT];      // bf16 hi part of W1@Wc [k][n]
__device__ __nv_bfloat16 g_Wl[D_IN * D_OUT];      // bf16 lo part
__device__ float g_h[(size_t)N_ROWS_PAD * D_OUT]; // x@W2 + c2 (padded rows)
__device__ float g_outf[(size_t)N_NODES * D_OUT]; // aggregated node embeddings
__device__ float g_dinv[N_NODES];
__device__ int   g_cnt[N_NODES];
__device__ int   g_off[N_NODES];
__device__ int   g_cursor[N_NODES];
__device__ int   g_srcs[N_POS];
__device__ int   g_part[SCAN_NBLK];

// ---------------------------------------------------------------- weight fuse + pack (one pass)
// W2 = W1@Wc -> split to bf16 hi/lo; c2 = b1@Wc.
__global__ void k_fusepack(const float* __restrict__ W1, const float* __restrict__ Wc,
                           const float* __restrict__ b1) {
    int idx = blockIdx.x * blockDim.x + threadIdx.x;
    if (idx >= D_IN * D_OUT) return;
    int k = idx >> 7, j = idx & 127;
    float acc = 0.f;
    #pragma unroll 8
    for (int m = 0; m < D_IN; ++m)
        acc = fmaf(W1[k * D_IN + m], Wc[m * D_OUT + j], acc);
    __nv_bfloat16 h = __float2bfloat16_rn(acc);
    g_Wh[idx] = h;
    g_Wl[idx] = __float2bfloat16_rn(acc - __bfloat162float(h));
    if (idx < D_OUT) {
        float c = 0.f;
        for (int m = 0; m < D_IN; ++m)
            c = fmaf(b1[m], Wc[m * D_OUT + idx], c);
        g_c2[idx] = c;
    }
}

// ---------------------------------------------------------------- degree count
__global__ void k_zero_cnt() {
    int i = blockIdx.x * blockDim.x + threadIdx.x;
    if (i < N_NODES) g_cnt[i] = 0;
}

__global__ void k_count(const int* __restrict__ pos) {
    int e = blockIdx.x * blockDim.x + threadIdx.x;
    if (e < N_POS) atomicAdd(&g_cnt[pos[N_POS + e]], 1);
}

// ---------------------------------------------------------------- parallel scan
__global__ __launch_bounds__(1024) void k_scan1() {
    __shared__ int warp_sum[32];
    int tid  = threadIdx.x;
    int lane = tid & 31;
    int wid  = tid >> 5;
    int i = blockIdx.x * 1024 + tid;
    int v = (i < N_NODES) ? g_cnt[i] : 0;
    int s = v;
    #pragma unroll
    for (int o = 1; o < 32; o <<= 1) {
        int t = __shfl_up_sync(0xFFFFFFFFu, s, o);
        if (lane >= o) s += t;
    }
    if (lane == 31) warp_sum[wid] = s;
    __syncthreads();
    if (wid == 0) {
        int ws = warp_sum[lane];
        int t2 = ws;
        #pragma unroll
        for (int o = 1; o < 32; o <<= 1) {
            int t = __shfl_up_sync(0xFFFFFFFFu, t2, o);
            if (lane >= o) t2 += t;
        }
        warp_sum[lane] = t2 - ws;
        if (lane == 31) g_part[blockIdx.x] = t2;
    }
    __syncthreads();
    if (i < N_NODES) {
        g_off[i]  = warp_sum[wid] + s - v;
        g_dinv[i] = rsqrtf((float)v + 1.0f);
    }
}

// scan phase 2+3 fused: each thread sums chunk partials (<=48 L2-broadcast ints)
__global__ void k_scan3() {
    int i = blockIdx.x * blockDim.x + threadIdx.x;
    if (i >= N_NODES) return;
    int chunk = i >> 10;
    int base = 0;
    for (int b = 0; b < chunk; ++b) base += g_part[b];
    int o = g_off[i] + base;
    g_off[i] = o;
    g_cursor[i] = o;
}

// ---------------------------------------------------------------- CSR fill
__global__ void k_fill(const int* __restrict__ pos) {
    int e = blockIdx.x * blockDim.x + threadIdx.x;
    if (e >= N_POS) return;
    int r = pos[e];
    int c = pos[N_POS + e];
    int p = atomicAdd(&g_cursor[c], 1);
    g_srcs[p] = r;
}

// ---------------------------------------------------------------- tensor-core GEMM (wmma bf16 hi/lo, pipelined)
// h = x @ W2 + c2 ; dropped xl*Wl term ~2^-16 relative.
__global__ __launch_bounds__(256) void k_gemm_tc(const float* __restrict__ x) {
    extern __shared__ char smem[];
    __nv_bfloat16* sBh = (__nv_bfloat16*)smem;           // [256][BPAD]
    __nv_bfloat16* sBl = sBh + 256 * BPAD;               // [256][BPAD]
    __nv_bfloat16* sA  = sBl + 256 * BPAD;               // 4 images [buf][hl][128][APAD]
    float*         sBias = (float*)(sA + 4 * 128 * APAD);// [16][BPAD]

    int tid = threadIdx.x;
    int wid = tid >> 5;
    int warp_m = wid >> 2;        // 0..1 (64 rows each)
    int warp_n = wid & 3;         // 0..3 (32 cols each)
    int row0 = blockIdx.x * BMT;

    // load B (hi+lo) into padded smem, bias tile
    {
        const uint4* srcH = (const uint4*)g_Wh;
        const uint4* srcL = (const uint4*)g_Wl;
        #pragma unroll 4
        for (int i = tid; i < 256 * 16; i += 256) {
            int r = i >> 4, c8 = i & 15;
            *(uint4*)&sBh[r * BPAD + c8 * 8] = srcH[i];
            *(uint4*)&sBl[r * BPAD + c8 * 8] = srcL[i];
        }
        for (int i = tid; i < 16 * 128; i += 256) {
            int r = i >> 7, c = i & 127;
            sBias[r * BPAD + c] = g_c2[c];
        }
    }
    __syncthreads();

    // accumulators initialized from replicated bias rows
    wmma::fragment<wmma::accumulator, 16, 16, 16, float> acc[4][2];
    #pragma unroll
    for (int m = 0; m < 4; ++m)
        #pragma unroll
        for (int n = 0; n < 2; ++n)
            wmma::load_matrix_sync(acc[m][n], sBias + warp_n * 32 + n * 16, BPAD,
                                   wmma::mem_row_major);

    // pipeline stages: ldx -> regs, cvt+sts -> A buffer
    int ar = tid >> 1;                 // row in tile (0..127)
    int h16 = (tid & 1) * 16;          // k offset within chunk
    int grow = row0 + ar;
    bool valid = grow < N_NODES;
    const float* xrow = x + (size_t)grow * D_IN + h16;
    float v[16];

    auto ldx = [&](int k0) {
        if (valid) {
            const float4* p = (const float4*)(xrow + k0);
            #pragma unroll
            for (int q = 0; q < 4; ++q) {
                float4 f = p[q];
                v[4 * q + 0] = f.x; v[4 * q + 1] = f.y;
                v[4 * q + 2] = f.z; v[4 * q + 3] = f.w;
            }
        } else {
            #pragma unroll
            for (int q = 0; q < 16; ++q) v[q] = 0.f;
        }
    };
    auto sts = [&](int buf) {
        uint32_t hp[8], lp[8];
        #pragma unroll
        for (int q = 0; q < 8; ++q) {
            __nv_bfloat16 h0 = __float2bfloat16_rn(v[2 * q]);
            __nv_bfloat16 h1 = __float2bfloat16_rn(v[2 * q + 1]);
            __nv_bfloat16 l0 = __float2bfloat16_rn(v[2 * q] - __bfloat162float(h0));
            __nv_bfloat16 l1 = __float2bfloat16_rn(v[2 * q + 1] - __bfloat162float(h1));
            hp[q] = (uint32_t)__bfloat16_as_ushort(h0) | ((uint32_t)__bfloat16_as_ushort(h1) << 16);
            lp[q] = (uint32_t)__bfloat16_as_ushort(l0) | ((uint32_t)__bfloat16_as_ushort(l1) << 16);
        }
        __nv_bfloat16* dH = sA + (size_t)(buf * 2 + 0) * 128 * APAD + ar * APAD + h16;
        __nv_bfloat16* dL = sA + (size_t)(buf * 2 + 1) * 128 * APAD + ar * APAD + h16;
        ((uint4*)dH)[0] = make_uint4(hp[0], hp[1], hp[2], hp[3]);
        ((uint4*)dH)[1] = make_uint4(hp[4], hp[5], hp[6], hp[7]);
        ((uint4*)dL)[0] = make_uint4(lp[0], lp[1], lp[2], lp[3]);
        ((uint4*)dL)[1] = make_uint4(lp[4], lp[5], lp[6], lp[7]);
    };

    ldx(0);
    sts(0);
    __syncthreads();

    for (int k0 = 0; k0 < 8; ++k0) {
        if (k0 < 7) ldx((k0 + 1) * 32);    // issue LDGs; latency hidden under MMAs

        const __nv_bfloat16* aH = sA + (size_t)((k0 & 1) * 2 + 0) * 128 * APAD;
        const __nv_bfloat16* aL = sA + (size_t)((k0 & 1) * 2 + 1) * 128 * APAD;
        #pragma unroll
        for (int kk = 0; kk < 32; kk += 16) {
            wmma::fragment<wmma::matrix_a, 16, 16, 16, __nv_bfloat16, wmma::row_major> ah[4], al[4];
            wmma::fragment<wmma::matrix_b, 16, 16, 16, __nv_bfloat16, wmma::row_major> bh[2], bl[2];
            #pragma unroll
            for (int m = 0; m < 4; ++m) {
                int arr = warp_m * 64 + m * 16;
                wmma::load_matrix_sync(ah[m], &aH[arr * APAD + kk], APAD);
                wmma::load_matrix_sync(al[m], &aL[arr * APAD + kk], APAD);
            }
            #pragma unroll
            for (int n = 0; n < 2; ++n) {
                int bcc = warp_n * 32 + n * 16;
                wmma::load_matrix_sync(bh[n], &sBh[(k0 * 32 + kk) * BPAD + bcc], BPAD);
                wmma::load_matrix_sync(bl[n], &sBl[(k0 * 32 + kk) * BPAD + bcc], BPAD);
            }
            #pragma unroll
            for (int m = 0; m < 4; ++m)
                #pragma unroll
                for (int n = 0; n < 2; ++n) {
                    wmma::mma_sync(acc[m][n], ah[m], bh[n], acc[m][n]);
                    wmma::mma_sync(acc[m][n], ah[m], bl[n], acc[m][n]);
                    wmma::mma_sync(acc[m][n], al[m], bh[n], acc[m][n]);
                }
        }

        if (k0 < 7) sts((k0 + 1) & 1);     // convert+store next buffer after MMAs
        __syncthreads();
    }

    // store directly (g_h is padded to 50048 rows -> no guards)
    #pragma unroll
    for (int m = 0; m < 4; ++m) {
        int row = row0 + warp_m * 64 + m * 16;
        #pragma unroll
        for (int n = 0; n < 2; ++n) {
            int col = warp_n * 32 + n * 16;
            wmma::store_matrix_sync(g_h + (size_t)row * D_OUT + col, acc[m][n],
                                    D_OUT, wmma::mem_row_major);
        }
    }
}

// ---------------------------------------------------------------- aggregate: one warp per node
// out[c] = bc + dinv[c] * ( dinv[c]*h[c] + sum_r dinv[r]*h[r] )
__global__ __launch_bounds__(256) void k_aggregate(const float* __restrict__ bc) {
    int node = (blockIdx.x * blockDim.x + threadIdx.x) >> 5;
    int lane = threadIdx.x & 31;
    if (node >= N_NODES) return;

    float dc = g_dinv[node];
    float4 hv = ((const float4*)g_h)[(size_t)node * 32 + lane];
    float4 acc = make_float4(dc * hv.x, dc * hv.y, dc * hv.z, dc * hv.w);

    int s0 = g_off[node];
    int cnt = g_cnt[node];
    #pragma unroll 4
    for (int j = 0; j < cnt; ++j) {
        int r = g_srcs[s0 + j];
        float w = g_dinv[r];
        float4 v = ((const float4*)g_h)[(size_t)r * 32 + lane];
        acc.x = fmaf(w, v.x, acc.x);
        acc.y = fmaf(w, v.y, acc.y);
        acc.z = fmaf(w, v.z, acc.z);
        acc.w = fmaf(w, v.w, acc.w);
    }

    float4 bv = ((const float4*)bc)[lane];
    float4 o = make_float4(fmaf(dc, acc.x, bv.x), fmaf(dc, acc.y, bv.y),
                           fmaf(dc, acc.z, bv.z), fmaf(dc, acc.w, bv.w));
    ((float4*)g_outf)[(size_t)node * 32 + lane] = o;
}

// ---------------------------------------------------------------- edge scoring
__global__ __launch_bounds__(256) void k_score(const int* __restrict__ ei,
                                               float* __restrict__ logits) {
    int gw = (blockIdx.x * blockDim.x + threadIdx.x) >> 5;
    int lane = threadIdx.x & 31;
    if (gw >= N_PRED) return;
    int a = ei[gw];
    int b = ei[N_PRED + gw];
    float4 va = ((const float4*)g_outf)[(size_t)a * 32 + lane];
    float4 vb = ((const float4*)g_outf)[(size_t)b * 32 + lane];
    float p = va.x * vb.x + va.y * vb.y + va.z * vb.z + va.w * vb.w;
    #pragma unroll
    for (int o = 16; o; o >>= 1) p += __shfl_xor_sync(0xFFFFFFFFu, p, o);
    if (lane == 0) logits[gw] = p;
}

// ----------------------------------------------------------------
extern "C" void kernel_launch(void* const* d_in, const int* in_sizes, int n_in,
                              void* d_out, int out_size) {
    const float* x   = (const float*)d_in[0];
    const int*   ei  = (const int*)d_in[1];
    const int*   pos = (const int*)d_in[2];
    const float* W1  = (const float*)d_in[3];
    const float* b1  = (const float*)d_in[4];
    const float* Wc  = (const float*)d_in[5];
    const float* bc  = (const float*)d_in[6];
    float* logits = (float*)d_out;

    static_assert(SMEM_TOTAL <= 227 * 1024, "smem budget");
    cudaFuncSetAttribute(k_gemm_tc, cudaFuncAttributeMaxDynamicSharedMemorySize, SMEM_TOTAL);

    // Fork a non-blocking side stream so the CSR build (atomic/L2-bound)
    // overlaps the GEMM chain (tensor/smem-bound).
    cudaStream_t s2;
    cudaEvent_t eFork, eJoin;
    cudaStreamCreateWithFlags(&s2, cudaStreamNonBlocking);
    cudaEventCreateWithFlags(&eFork, cudaEventDisableTiming);
    cudaEventCreateWithFlags(&eJoin, cudaEventDisableTiming);

    cudaEventRecord(eFork, 0);
    cudaStreamWaitEvent(s2, eFork, 0);

    // main stream: GEMM chain
    k_fusepack<<<(D_IN * D_OUT + 255) / 256, 256>>>(W1, Wc, b1);
    k_gemm_tc<<<NBLK_GEMM, 256, SMEM_TOTAL>>>(x);

    // side stream: CSR chain
    k_zero_cnt<<<(N_NODES + 255) / 256, 256, 0, s2>>>();
    k_count<<<(N_POS + 255) / 256, 256, 0, s2>>>(pos);
    k_scan1<<<SCAN_NBLK, 1024, 0, s2>>>();
    k_scan3<<<(N_NODES + 255) / 256, 256, 0, s2>>>();
    k_fill<<<(N_POS + 255) / 256, 256, 0, s2>>>(pos);
    cudaEventRecord(eJoin, s2);
    cudaStreamWaitEvent(0, eJoin, 0);

    // tail (needs both branches)
    k_aggregate<<<(N_NODES * 32 + 255) / 256, 256>>>(bc);
    k_score<<<(N_PRED * 32 + 255) / 256, 256>>>(ei, logits);

    // Destroy handles only when not capturing (destroying a forked stream
    // mid-capture invalidates the graph).
    cudaStreamCaptureStatus st = cudaStreamCaptureStatusNone;
    cudaStreamIsCapturing((cudaStream_t)0, &st);
    if (st == cudaStreamCaptureStatusNone) {
        cudaStreamDestroy(s2);
        cudaEventDestroy(eFork);
        cudaEventDestroy(eJoin);
    }
}